// round 13
// baseline (speedup 1.0000x reference)
#include <cuda_runtime.h>
#include <math.h>
#include <stdint.h>

// GRU: B=32, S=2048, H=512, 2 layers. fp32 (f32x2-packed math).
#define H   512
#define Bz  32
#define Sz  2048
#define G3  1536

// ---------------- static device scratch (no allocations allowed) -------------
__device__ float g_ip[(size_t)Sz * Bz * G3];   // input-projection buffer
__device__ float g_y0[(size_t)Sz * Bz * H];    // layer0 output, [s][b][h]
__device__ float g_h[2][Bz * H];               // hidden state (fallback path)
__device__ unsigned long long g_cnt4[4][16];   // fallback barrier arrivals
__device__ unsigned long long g_gen4[4][16];   // fallback barrier generation

// ---------------- packed f32x2 helpers (Blackwell) ---------------------------
#define FMA2(d, a, b, c) \
    asm("fma.rn.f32x2 %0, %1, %2, %3;" : "=l"(d) : "l"(a), "l"(b), "l"(c))

__device__ __forceinline__ unsigned long long pack2(float lo, float hi) {
    unsigned long long r;
    asm("mov.b64 %0, {%1, %2};" : "=l"(r) : "f"(lo), "f"(hi));
    return r;
}
__device__ __forceinline__ float2 unpack2(unsigned long long v) {
    float2 f;
    asm("mov.b64 {%0, %1}, %2;" : "=f"(f.x), "=f"(f.y) : "l"(v));
    return f;
}

// ---------------- cluster primitives -----------------------------------------
__device__ __forceinline__ uint32_t smem_u32(const void* p) {
    uint32_t a;
    asm("{ .reg .u64 t; cvta.to.shared.u64 t, %1; cvt.u32.u64 %0, t; }"
        : "=r"(a) : "l"(p));
    return a;
}
__device__ __forceinline__ uint32_t ctarank() {
    uint32_t r;
    asm("mov.u32 %0, %%cluster_ctarank;" : "=r"(r));
    return r;
}
__device__ __forceinline__ void cluster_sync_all() {
    asm volatile("barrier.cluster.arrive.aligned;" ::: "memory");
    asm volatile("barrier.cluster.wait.aligned;" ::: "memory");
}
// store one float into CTA `rank`'s shared memory at the same smem offset
__device__ __forceinline__ void st_cluster_f32(uint32_t addr, uint32_t rank, float v) {
    uint32_t r;
    asm volatile("mapa.shared::cluster.u32 %0, %1, %2;" : "=r"(r) : "r"(addr), "r"(rank));
    asm volatile("st.shared::cluster.f32 [%0], %1;" :: "r"(r), "f"(v) : "memory");
}

// ---------------- release/acquire primitives (fallback barrier) ---------------
__device__ __forceinline__ unsigned long long atom_add_release(unsigned long long* p) {
    unsigned long long old;
    asm volatile("atom.release.gpu.global.add.u64 %0, [%1], 1;"
                 : "=l"(old) : "l"(p) : "memory");
    return old;
}
__device__ __forceinline__ void red_add_release(unsigned long long* p) {
    asm volatile("red.release.gpu.global.add.u64 [%0], 1;" :: "l"(p) : "memory");
}
__device__ __forceinline__ unsigned long long ld_acquire(unsigned long long* p) {
    unsigned long long v;
    asm volatile("ld.acquire.gpu.global.u64 %0, [%1];" : "=l"(v) : "l"(p) : "memory");
    return v;
}

// ============================================================================
// PRIMARY: cluster scan. 16 CTAs cover all 512 j for 4 batches; 8 clusters.
// h lives in SMEM (double-buffered), exchanged via DSMEM; one HW cluster
// barrier per step. No global atomics, no global h.
// ============================================================================
#define CLU      16
#define SC_THR   384            // 12 warps
#define SC_JT    32             // j's per CTA
#define SC_BT    4              // batches per cluster
#define SC_ROWS  96             // 3 gates * SC_JT
#define SC_GTH   (SC_JT * SC_BT)   // 128 gate threads
#define SC_SMEM_FLOATS (SC_ROWS * H + 2 * SC_BT * H + SC_ROWS * SC_BT)
#define SC_SMEM_BYTES  (SC_SMEM_FLOATS * 4)   // 214528 B <= 227KB opt-in

__global__ __launch_bounds__(SC_THR, 1)
void gru_scan_cluster(const float* __restrict__ ip,   // [S][B][3H] (bi included)
                      const float* __restrict__ Wh,   // [3H][H]
                      const float* __restrict__ bh,   // [3H]
                      float* __restrict__ y,          // l0: [s][b][h]; l1: [b][s][h]
                      float* __restrict__ hout,       // last hidden (layer1 only)
                      int last_layer)
{
    extern __shared__ float sm[];
    float* w_s  = sm;                                   // [96][512]  192 KB
    float* h_s  = sm + SC_ROWS * H;                     // [2][4][512] 16 KB
    float* hp_s = sm + SC_ROWS * H + 2 * SC_BT * H;     // [96][4]    1.5 KB

    const int tid  = threadIdx.x;
    const int w    = tid >> 5;           // warp 0..11
    const int lane = tid & 31;
    const uint32_t rank = ctarank();     // 0..15 (j-tile)
    const int cid  = blockIdx.x / CLU;   // 0..7  (batch group)
    const int j0   = (int)rank * SC_JT;
    const int b0   = cid * SC_BT;

    // ---- load this CTA's 96 Wh rows into SMEM (once) ------------------------
    for (int idx = tid; idx < SC_ROWS * (H / 4); idx += SC_THR) {
        int r  = idx / (H / 4);
        int kc = idx % (H / 4);
        int grow = (r >> 5) * H + j0 + (r & 31);
        ((float4*)w_s)[r * (H / 4) + kc] =
            ((const float4*)Wh)[(size_t)grow * (H / 4) + kc];
    }
    for (int idx = tid; idx < 2 * SC_BT * H; idx += SC_THR) h_s[idx] = 0.f;

    // ---- gate-thread constants (threads 0..127: one (j,b) output each) ------
    float bhr = 0.f, bhz = 0.f, bhn = 0.f;
    int g_jl = 0, g_bb = 0, bglob = 0;
    const float* ipp = ip;
    const bool gthread = (tid < SC_GTH);
    if (gthread) {
        g_jl  = tid >> 2;            // 0..31
        g_bb  = tid & 3;             // 0..3
        bglob = b0 + g_bb;
        int j = j0 + g_jl;
        bhr = __ldg(bh + j); bhz = __ldg(bh + H + j); bhn = __ldg(bh + 2 * H + j);
        ipp = ip + (size_t)bglob * G3 + (j0 + g_jl);
    }
    float ipr = 0.f, ipz = 0.f, ipn = 0.f;
    if (gthread) {                   // prefetch ip for t=0
        ipr = __ldg(ipp);
        ipz = __ldg(ipp + H);
        ipn = __ldg(ipp + 2 * H);
    }

    const uint32_t h_u32 = smem_u32(h_s);
    const int r0 = w * 8;            // this warp's 8 rows

    cluster_sync_all();              // buffers + weights ready cluster-wide

    const unsigned long long* w2 = (const unsigned long long*)w_s;

    for (int t = 0; t < Sz; t++) {
        const unsigned long long* hb =
            (const unsigned long long*)(h_s + (t & 1) * SC_BT * H);

        // ---- hp = Wh_tile @ h : warp = 8 rows x 4 batches, lanes split k ----
        unsigned long long acc[8][4];
        #pragma unroll
        for (int rr = 0; rr < 8; rr++)
            #pragma unroll
            for (int b = 0; b < 4; b++) acc[rr][b] = 0ULL;

        #pragma unroll
        for (int i = 0; i < 8; i++) {
            int p = lane + 32 * i;
            unsigned long long hv[4];
            #pragma unroll
            for (int b = 0; b < 4; b++) hv[b] = hb[b * (H / 2) + p];
            #pragma unroll
            for (int rr = 0; rr < 8; rr++) {
                unsigned long long wv = w2[(r0 + rr) * (H / 2) + p];
                #pragma unroll
                for (int b = 0; b < 4; b++)
                    FMA2(acc[rr][b], wv, hv[b], acc[rr][b]);
            }
        }
        #pragma unroll
        for (int rr = 0; rr < 8; rr++)
            #pragma unroll
            for (int b = 0; b < 4; b++) {
                float2 f = unpack2(acc[rr][b]);
                float v = f.x + f.y;
                v += __shfl_xor_sync(0xffffffffu, v, 16);
                v += __shfl_xor_sync(0xffffffffu, v, 8);
                v += __shfl_xor_sync(0xffffffffu, v, 4);
                v += __shfl_xor_sync(0xffffffffu, v, 2);
                v += __shfl_xor_sync(0xffffffffu, v, 1);
                if (lane == 0) hp_s[(r0 + rr) * SC_BT + b] = v;
            }
        __syncthreads();

        // ---- gates + state update + DSMEM broadcast -------------------------
        if (gthread) {
            float hpr = hp_s[g_jl * SC_BT + g_bb] + bhr;
            float hpz = hp_s[(SC_JT + g_jl) * SC_BT + g_bb] + bhz;
            float hpn = hp_s[(2 * SC_JT + g_jl) * SC_BT + g_bb] + bhn;
            int j = j0 + g_jl;
            float hprev = h_s[(t & 1) * SC_BT * H + g_bb * H + j];
            float r = 1.f / (1.f + __expf(-(ipr + hpr)));
            float z = 1.f / (1.f + __expf(-(ipz + hpz)));
            float n = tanhf(ipn + r * hpn);
            float hy = (1.f - z) * n + z * hprev;
            if (last_layer) {
                y[((size_t)bglob * Sz + t) * H + j] = hy;
                if (t == Sz - 1) hout[bglob * H + j] = hy;
            } else {
                y[((size_t)t * Bz + bglob) * H + j] = hy;
            }
            if (t != Sz - 1) {
                uint32_t off = h_u32 +
                    (uint32_t)((((t + 1) & 1) * SC_BT + g_bb) * H + j) * 4u;
                #pragma unroll
                for (int rr = 0; rr < CLU; rr++)
                    st_cluster_f32(off, (uint32_t)rr, hy);
                const float* p = ipp + (size_t)(t + 1) * (Bz * G3);
                ipr = __ldg(p);
                ipz = __ldg(p + H);
                ipn = __ldg(p + 2 * H);
            }
        }
        cluster_sync_all();
    }
}

// ============================================================================
// FALLBACK: measured-good (R6) scan — register Wh, global release/acquire
// barrier over 32-block batch-groups. Used only if the 16-CTA cluster config
// is not launchable on this device.
// ============================================================================
#define NBLK 128
#define NTHR 256
#define JT   16
#define BT   8
#define ROWS 48
#define GRPBLK 32

__device__ __forceinline__ void group_barrier(int grp)
{
    __syncthreads();
    if (threadIdx.x == NTHR - 1) {
        unsigned long long old = atom_add_release(&g_cnt4[grp][0]);
        unsigned long long epoch = old >> 5;
        if ((old & (GRPBLK - 1)) == GRPBLK - 1) {
            red_add_release(&g_gen4[grp][0]);
        } else {
            while (ld_acquire(&g_gen4[grp][0]) <= epoch) { }
        }
    }
    __syncthreads();
}

__global__ __launch_bounds__(NTHR, 1)
void gru_scan_fallback(const float* __restrict__ ip,
                       const float* __restrict__ Wh,
                       const float* __restrict__ bh,
                       float* __restrict__ y,
                       float* __restrict__ hout,
                       int last_layer)
{
    __shared__ __align__(16) float h_s[BT * H];
    __shared__ float hp_s[ROWS * BT];

    const int tid  = threadIdx.x;
    const int w    = tid >> 5;
    const int lane = tid & 31;
    const int bid  = blockIdx.x;
    const int jt   = bid >> 2;
    const int bt   = bid & 3;
    const int j0   = jt * JT;
    const int b0   = bt * BT;

    unsigned long long wreg[6][8];
    #pragma unroll
    for (int rr = 0; rr < 6; rr++) {
        int r_loc = w * 6 + rr;
        int grow  = (r_loc >> 4) * H + j0 + (r_loc & 15);
        const unsigned long long* src =
            (const unsigned long long*)(Wh + (size_t)grow * H);
        #pragma unroll
        for (int i = 0; i < 8; i++)
            wreg[rr][i] = __ldg(src + lane + 32 * i);
    }

    float bhr = 0.f, bhz = 0.f, bhn = 0.f;
    int g_jl = 0, g_bb = 0, bglob = 0;
    const float* ipp = ip;
    const bool gthread = (tid < JT * BT);
    if (gthread) {
        g_jl  = tid >> 3;
        g_bb  = tid & 7;
        bglob = b0 + g_bb;
        int j = j0 + g_jl;
        bhr = __ldg(bh + j); bhz = __ldg(bh + H + j); bhn = __ldg(bh + 2 * H + j);
        ipp = ip + (size_t)bglob * G3 + (j0 + g_jl);
    }
    float ipr = 0.f, ipz = 0.f, ipn = 0.f;
    if (gthread) {
        ipr = __ldg(ipp);
        ipz = __ldg(ipp + H);
        ipn = __ldg(ipp + 2 * H);
    }

    const unsigned long long* h2 = (const unsigned long long*)h_s;

    for (int t = 0; t < Sz; t++) {
        {
            const float4* hsrc = (const float4*)(&g_h[t & 1][b0 * H]);
            float4* hdst = (float4*)h_s;
            #pragma unroll
            for (int i = 0; i < (BT * H / 4) / NTHR; i++) {
                int idx = tid + i * NTHR;
                float4 v;
                if (t == 0) v = make_float4(0.f, 0.f, 0.f, 0.f);
                else        v = __ldcg(hsrc + idx);
                hdst[idx] = v;
            }
        }
        __syncthreads();

        unsigned long long acc[6][8];
        #pragma unroll
        for (int rr = 0; rr < 6; rr++)
            #pragma unroll
            for (int b = 0; b < 8; b++) acc[rr][b] = 0ULL;

        #pragma unroll
        for (int i = 0; i < 8; i++) {
            int p = lane + 32 * i;
            unsigned long long hv[8];
            #pragma unroll
            for (int b = 0; b < 8; b++) hv[b] = h2[b * (H / 2) + p];
            #pragma unroll
            for (int rr = 0; rr < 6; rr++)
                #pragma unroll
                for (int b = 0; b < 8; b++)
                    FMA2(acc[rr][b], wreg[rr][i], hv[b], acc[rr][b]);
        }

        #pragma unroll
        for (int rr = 0; rr < 6; rr++)
            #pragma unroll
            for (int b = 0; b < 8; b++) {
                float2 f = unpack2(acc[rr][b]);
                float v = f.x + f.y;
                v += __shfl_xor_sync(0xffffffffu, v, 16);
                v += __shfl_xor_sync(0xffffffffu, v, 8);
                v += __shfl_xor_sync(0xffffffffu, v, 4);
                v += __shfl_xor_sync(0xffffffffu, v, 2);
                v += __shfl_xor_sync(0xffffffffu, v, 1);
                if (lane == 0) hp_s[(w * 6 + rr) * BT + b] = v;
            }
        __syncthreads();

        if (gthread) {
            float hpr = hp_s[g_jl * BT + g_bb] + bhr;
            float hpz = hp_s[(JT + g_jl) * BT + g_bb] + bhz;
            float hpn = hp_s[(2 * JT + g_jl) * BT + g_bb] + bhn;
            float hprev = h_s[g_bb * H + (j0 + g_jl)];
            float r = 1.f / (1.f + __expf(-(ipr + hpr)));
            float z = 1.f / (1.f + __expf(-(ipz + hpz)));
            float n = tanhf(ipn + r * hpn);
            float hy = (1.f - z) * n + z * hprev;
            int j = j0 + g_jl;
            __stcg(&g_h[(t + 1) & 1][bglob * H + j], hy);
            if (last_layer) {
                y[((size_t)bglob * Sz + t) * H + j] = hy;
                if (t == Sz - 1) hout[bglob * H + j] = hy;
            } else {
                y[((size_t)t * Bz + bglob) * H + j] = hy;
            }
            if (t != Sz - 1) {
                const float* p = ipp + (size_t)(t + 1) * (Bz * G3);
                ipr = __ldg(p);
                ipz = __ldg(p + H);
                ipn = __ldg(p + 2 * H);
            }
        }
        if (t != Sz - 1) group_barrier(bt);
    }
}

// ---------------- fp32 input-projection GEMM (f32x2 + double-buffered) -------
#define GBM 128
#define GBN 128
#define GBK 8

__global__ __launch_bounds__(256, 1)
void gemm_wi_kernel(const float* __restrict__ A, const float* __restrict__ W,
                    const float* __restrict__ bias, float* __restrict__ C,
                    int strideB, int strideS)
{
    __shared__ __align__(16) float As[2][GBK][GBM];
    __shared__ __align__(16) float Bs[2][GBK][GBN];

    const int tid = threadIdx.x;
    const int m0 = blockIdx.y * GBM;
    const int n0 = blockIdx.x * GBN;
    const int ty = tid >> 4, tx = tid & 15;

    const int lrow = tid >> 1;
    const int lk   = (tid & 1) * 4;

    const int am = m0 + lrow;
    const size_t aoff = (size_t)(am & 31) * strideB + (size_t)(am >> 5) * strideS;
    const size_t boff = (size_t)(n0 + lrow) * H;

    unsigned long long acc2[8][4];
    #pragma unroll
    for (int i = 0; i < 8; i++)
        #pragma unroll
        for (int j = 0; j < 4; j++) acc2[i][j] = 0ULL;

    {
        float4 av = *(const float4*)(A + aoff + lk);
        float4 bv = *(const float4*)(W + boff + lk);
        As[0][lk + 0][lrow] = av.x; As[0][lk + 1][lrow] = av.y;
        As[0][lk + 2][lrow] = av.z; As[0][lk + 3][lrow] = av.w;
        Bs[0][lk + 0][lrow] = bv.x; Bs[0][lk + 1][lrow] = bv.y;
        Bs[0][lk + 2][lrow] = bv.z; Bs[0][lk + 3][lrow] = bv.w;
    }
    __syncthreads();

    int buf = 0;
    for (int k0 = 0; k0 < H; k0 += GBK) {
        float4 av, bv;
        const bool more = (k0 + GBK < H);
        if (more) {
            av = *(const float4*)(A + aoff + k0 + GBK + lk);
            bv = *(const float4*)(W + boff + k0 + GBK + lk);
        }

        #pragma unroll
        for (int k = 0; k < GBK; k++) {
            float4 a0 = *(float4*)&As[buf][k][ty * 8];
            float4 a1 = *(float4*)&As[buf][k][ty * 8 + 4];
            float4 b0 = *(float4*)&Bs[buf][k][tx * 8];
            float4 b1 = *(float4*)&Bs[buf][k][tx * 8 + 4];
            unsigned long long a2[8];
            a2[0] = pack2(a0.x, a0.x); a2[1] = pack2(a0.y, a0.y);
            a2[2] = pack2(a0.z, a0.z); a2[3] = pack2(a0.w, a0.w);
            a2[4] = pack2(a1.x, a1.x); a2[5] = pack2(a1.y, a1.y);
            a2[6] = pack2(a1.z, a1.z); a2[7] = pack2(a1.w, a1.w);
            unsigned long long b2[4];
            b2[0] = pack2(b0.x, b0.y); b2[1] = pack2(b0.z, b0.w);
            b2[2] = pack2(b1.x, b1.y); b2[3] = pack2(b1.z, b1.w);
            #pragma unroll
            for (int i = 0; i < 8; i++)
                #pragma unroll
                for (int j = 0; j < 4; j++)
                    FMA2(acc2[i][j], a2[i], b2[j], acc2[i][j]);
        }

        if (more) {
            int nb = buf ^ 1;
            As[nb][lk + 0][lrow] = av.x; As[nb][lk + 1][lrow] = av.y;
            As[nb][lk + 2][lrow] = av.z; As[nb][lk + 3][lrow] = av.w;
            Bs[nb][lk + 0][lrow] = bv.x; Bs[nb][lk + 1][lrow] = bv.y;
            Bs[nb][lk + 2][lrow] = bv.z; Bs[nb][lk + 3][lrow] = bv.w;
            __syncthreads();
            buf = nb;
        }
    }

    float bia[8];
    #pragma unroll
    for (int j = 0; j < 8; j++) bia[j] = __ldg(bias + n0 + tx * 8 + j);

    #pragma unroll
    for (int i = 0; i < 8; i++) {
        int m = m0 + ty * 8 + i;
        float* crow = C + (size_t)m * G3 + n0 + tx * 8;
        float2 p0 = unpack2(acc2[i][0]);
        float2 p1 = unpack2(acc2[i][1]);
        float2 p2 = unpack2(acc2[i][2]);
        float2 p3 = unpack2(acc2[i][3]);
        float4 o0 = make_float4(p0.x + bia[0], p0.y + bia[1],
                                p1.x + bia[2], p1.y + bia[3]);
        float4 o1 = make_float4(p2.x + bia[4], p2.y + bia[5],
                                p3.x + bia[6], p3.y + bia[7]);
        *(float4*)(crow)     = o0;
        *(float4*)(crow + 4) = o1;
    }
}

// ---------------- launch ------------------------------------------------------
static bool cluster_ok()
{
    cudaFuncSetAttribute(gru_scan_cluster,
                         cudaFuncAttributeMaxDynamicSharedMemorySize, SC_SMEM_BYTES);
    cudaFuncSetAttribute(gru_scan_cluster,
                         cudaFuncAttributeNonPortableClusterSizeAllowed, 1);
    cudaLaunchConfig_t cfg = {};
    cfg.gridDim  = dim3(8 * CLU, 1, 1);
    cfg.blockDim = dim3(SC_THR, 1, 1);
    cfg.dynamicSmemBytes = SC_SMEM_BYTES;
    cudaLaunchAttribute at[1];
    at[0].id = cudaLaunchAttributeClusterDimension;
    at[0].val.clusterDim.x = CLU;
    at[0].val.clusterDim.y = 1;
    at[0].val.clusterDim.z = 1;
    cfg.attrs = at;
    cfg.numAttrs = 1;
    int ncl = 0;
    cudaError_t e = cudaOccupancyMaxActiveClusters(&ncl, gru_scan_cluster, &cfg);
    if (e != cudaSuccess) { (void)cudaGetLastError(); return false; }  // clear sticky error
    return ncl >= 8;
}

static void launch_scan(bool use_cluster, const float* ip, const float* Wh,
                        const float* bh, float* y, float* hout, int last_layer)
{
    if (use_cluster) {
        cudaLaunchConfig_t cfg = {};
        cfg.gridDim  = dim3(8 * CLU, 1, 1);     // 128 CTAs = 8 clusters of 16
        cfg.blockDim = dim3(SC_THR, 1, 1);
        cfg.dynamicSmemBytes = SC_SMEM_BYTES;
        cfg.stream = 0;
        cudaLaunchAttribute at[1];
        at[0].id = cudaLaunchAttributeClusterDimension;
        at[0].val.clusterDim.x = CLU;
        at[0].val.clusterDim.y = 1;
        at[0].val.clusterDim.z = 1;
        cfg.attrs = at;
        cfg.numAttrs = 1;
        cudaLaunchKernelEx(&cfg, gru_scan_cluster, ip, Wh, bh, y, hout, last_layer);
    } else {
        gru_scan_fallback<<<NBLK, NTHR>>>(ip, Wh, bh, y, hout, last_layer);
    }
}

extern "C" void kernel_launch(void* const* d_in, const int* in_sizes, int n_in,
                              void* d_out, int out_size)
{
    const float* x   = (const float*)d_in[0];
    const float* Wi0 = (const float*)d_in[1];
    const float* bi0 = (const float*)d_in[2];
    const float* Wh0 = (const float*)d_in[3];
    const float* bh0 = (const float*)d_in[4];
    const float* Wi1 = (const float*)d_in[5];
    const float* bi1 = (const float*)d_in[6];
    const float* Wh1 = (const float*)d_in[7];
    const float* bh1 = (const float*)d_in[8];
    float* out = (float*)d_out;

    float *ip, *y0;
    cudaGetSymbolAddress((void**)&ip, g_ip);
    cudaGetSymbolAddress((void**)&y0, g_y0);

    const bool use_cluster = cluster_ok();   // deterministic host-side choice

    dim3 gg(G3 / GBN, (Bz * Sz) / GBM);   // 12 x 512

    // layer 0: ip = x @ Wi0^T + bi0, then scan
    gemm_wi_kernel<<<gg, 256>>>(x, Wi0, bi0, ip, Sz * H, H);
    launch_scan(use_cluster, ip, Wh0, bh0, y0, nullptr, 0);

    // layer 1: ip = y0 @ Wi1^T + bi1 (y0 is [s][b][h] -> rows contiguous), then scan
    gemm_wi_kernel<<<gg, 256>>>(y0, Wi1, bi1, ip, H, Bz * H);
    launch_scan(use_cluster, ip, Wh1, bh1, out, out + (size_t)Bz * Sz * H, 1);

    (void)in_sizes; (void)n_in; (void)out_size;
}